// round 17
// baseline (speedup 1.0000x reference)
#include <cuda_runtime.h>
#include <cuda_fp16.h>
#include <cstdint>

#define NNODES 10240
#define NGRAPH 64
#define HID 512
#define HEADS 8
#define HDIM 64
#define MAXC 384

#define KC 64                // halves per K-chunk (128B per row)
#define NCH 8                // K = 512 everywhere
#define NSTAGE 2             // double buffer

// ---------------------------------------------------------------------------
// Scratch (device globals: no allocation allowed)
// ---------------------------------------------------------------------------
__device__ __align__(16) __half g_QKVh[(size_t)NNODES * 1536];    // Q|K|V fp16
__device__ __align__(16) __half g_Xh[(size_t)NNODES * HID];       // x hi / O fp16
__device__ __align__(16) __half g_Wh[4][(size_t)HID * HID];       // wq,wk,wv,wo fp16
__device__ float g_bcat[3 * HID];
__device__ int g_start[NGRAPH + 2];

// ---------------------------------------------------------------------------
__device__ __forceinline__ uint32_t smem_u32(const void* p) {
    uint32_t a;
    asm("{ .reg .u64 t; cvta.to.shared.u64 t, %1; cvt.u32.u64 %0, t; }" : "=r"(a) : "l"(p));
    return a;
}

// ---------------------------------------------------------------------------
// Fused prep: W fp16-convert, x fp16-convert, segment starts, bias concat.
// ---------------------------------------------------------------------------
#define PREP_W   (4 * HID * HID)            // 1048576
#define PREP_X   (NNODES * HID)             // 5242880
#define PREP_TOT (PREP_W + PREP_X + NNODES + HID)

__global__ void prep_kernel(
    const float* __restrict__ X, const void* bptr,
    const float* __restrict__ w0, const float* __restrict__ w1,
    const float* __restrict__ w2, const float* __restrict__ w3,
    const float* __restrict__ bq, const float* __restrict__ bk,
    const float* __restrict__ bv,
    __half* __restrict__ Xh, __half* __restrict__ Wh)
{
    int i = blockIdx.x * blockDim.x + threadIdx.x;
    if (i < PREP_W) {
        int m = i >> 18;
        int local = i & 262143;
        const float* W = (m == 0) ? w0 : (m == 1) ? w1 : (m == 2) ? w2 : w3;
        Wh[i] = __float2half(W[local]);
    } else if (i < PREP_W + PREP_X) {
        int j = i - PREP_W;
        Xh[j] = __float2half(X[j]);
    } else if (i < PREP_W + PREP_X + NNODES) {
        int j = i - PREP_W - PREP_X;
        const int* b32 = (const int*)bptr;
        const long long* b64 = (const long long*)bptr;
        const bool is64 = (b32[NNODES - 1] == 0);
        int bi = is64 ? (int)b64[j] : b32[j];
        int bp = (j == 0) ? -1 : (is64 ? (int)b64[j - 1] : b32[j - 1]);
        for (int g = bp + 1; g <= bi; ++g) g_start[g] = j;
        if (j == NNODES - 1)
            for (int g = bi + 1; g <= NGRAPH; ++g) g_start[g] = NNODES;
    } else if (i < PREP_TOT) {
        int j = i - PREP_W - PREP_X - NNODES;
        g_bcat[j] = bq[j];
        g_bcat[HID + j] = bk[j];
        g_bcat[2 * HID + j] = bv[j];
    }
}

// ---------------------------------------------------------------------------
// HMMA GEMM: C[M, N] = A[M,512](fp16) * B[N,512](fp16)^T + bias.
// BM=64 x BN CTA tile, 4 warps (2m x 2n), mma.sync.m16n8k16, XOR-swizzled
// smem, 2-stage cp.async ring, ONE barrier per chunk. NEW: double-buffered
// fragment registers — k-step ks+1's ldmatrix issue before ks's MMAs, so
// smem latency overlaps tensor work (the measured stall: tensor=43%,
// latency-bound). Arithmetic order unchanged.
// ---------------------------------------------------------------------------
template <int BM, int BN, bool HALFOUT>
__global__ __launch_bounds__(128, BN == 128 ? 3 : 5) void gemm_hmma(
    const __half* __restrict__ A, const __half* __restrict__ B,
    const float* __restrict__ bias, float* __restrict__ Cf,
    __half* __restrict__ Ch, int ldc)
{
    constexpr int MT = BM / 32;            // m-subtiles (16 rows) per warp
    constexpr int NT = BN / 16;            // n-subtiles (8 cols) per warp
    constexpr int STG_A = BM * 128;
    constexpr int STG_B = BN * 128;
    constexpr int STAGE = STG_A + STG_B;

    extern __shared__ char sm_raw[];
    const int tid = threadIdx.x;
    const int wid = tid >> 5, lane = tid & 31;
    const int bm = blockIdx.y * BM, bn = blockIdx.x * BN;
    const int wm = (wid & 1) * (BM / 2);
    const int wn = (wid >> 1) * (BN / 2);
    const uint32_t sbase = smem_u32(sm_raw);

    float acc[MT][NT][4];
#pragma unroll
    for (int a = 0; a < MT; a++)
#pragma unroll
        for (int b = 0; b < NT; b++)
#pragma unroll
            for (int c = 0; c < 4; c++) acc[a][b][c] = 0.f;

    const int lr = tid >> 3;      // 0..15 row group
    const int ls = tid & 7;       // 0..7 16B segment

    auto issue = [&](int ch) {
        const __half* gA = A + (size_t)bm * HID + ch * KC;
        const __half* gB = B + (size_t)bn * HID + ch * KC;
        uint32_t sA = sbase + (ch % NSTAGE) * STAGE;
        uint32_t sB = sA + STG_A;
#pragma unroll
        for (int t = 0; t < BM / 16; t++) {
            int row = lr + t * 16;
            uint32_t off = row * 128 + ((ls ^ (row & 7)) * 16);
            asm volatile("cp.async.cg.shared.global [%0], [%1], 16;"
                         :: "r"(sA + off), "l"(gA + (size_t)row * HID + ls * 8));
        }
#pragma unroll
        for (int t = 0; t < BN / 16; t++) {
            int row = lr + t * 16;
            uint32_t off = row * 128 + ((ls ^ (row & 7)) * 16);
            asm volatile("cp.async.cg.shared.global [%0], [%1], 16;"
                         :: "r"(sB + off), "l"(gB + (size_t)row * HID + ls * 8));
        }
        asm volatile("cp.async.commit_group;");
    };

    issue(0);

    const int lrow = lane & 15;
    const int lseg = lane >> 4;

    uint32_t arb[2][MT][4];        // double-buffered A fragments
    uint32_t brb[2][NT / 2][4];    // double-buffered B fragments

    for (int ch = 0; ch < NCH; ++ch) {
        asm volatile("cp.async.wait_group 0;");
        __syncthreads();
        if (ch + 1 < NCH) issue(ch + 1);   // overlaps with compute below

        const uint32_t sA = sbase + (ch % NSTAGE) * STAGE;
        const uint32_t sB = sA + STG_A;

        // fragment loader for k-step ks (ks = 0..3; 16 halves each)
        auto ldfr = [&](int ks, int buf) {
            const int seg = ks * 2 + lseg;
#pragma unroll
            for (int mt = 0; mt < MT; mt++) {
                int row = wm + mt * 16 + lrow;
                uint32_t addr = sA + row * 128 + ((seg ^ (row & 7)) * 16);
                asm volatile("ldmatrix.sync.aligned.m8n8.x4.shared.b16 {%0,%1,%2,%3}, [%4];"
                             : "=r"(arb[buf][mt][0]), "=r"(arb[buf][mt][1]),
                               "=r"(arb[buf][mt][2]), "=r"(arb[buf][mt][3])
                             : "r"(addr));
            }
#pragma unroll
            for (int nt2 = 0; nt2 < NT / 2; nt2++) {
                int row = wn + nt2 * 16 + lrow;
                uint32_t addr = sB + row * 128 + ((seg ^ (row & 7)) * 16);
                asm volatile("ldmatrix.sync.aligned.m8n8.x4.shared.b16 {%0,%1,%2,%3}, [%4];"
                             : "=r"(brb[buf][nt2][0]), "=r"(brb[buf][nt2][1]),
                               "=r"(brb[buf][nt2][2]), "=r"(brb[buf][nt2][3])
                             : "r"(addr));
            }
        };

        ldfr(0, 0);
#pragma unroll
        for (int ks = 0; ks < 4; ks++) {
            if (ks < 3) ldfr(ks + 1, (ks + 1) & 1);  // prefetch next k-step
            const int cur = ks & 1;
#pragma unroll
            for (int mt = 0; mt < MT; mt++)
#pragma unroll
                for (int nt = 0; nt < NT; nt++) {
                    uint32_t b0 = brb[cur][nt >> 1][nt & 1];
                    uint32_t b1 = brb[cur][nt >> 1][(nt & 1) + 2];
                    asm volatile(
                        "mma.sync.aligned.m16n8k16.row.col.f32.f16.f16.f32 "
                        "{%0,%1,%2,%3}, {%4,%5,%6,%7}, {%8,%9}, {%0,%1,%2,%3};"
                        : "+f"(acc[mt][nt][0]), "+f"(acc[mt][nt][1]),
                          "+f"(acc[mt][nt][2]), "+f"(acc[mt][nt][3])
                        : "r"(arb[cur][mt][0]), "r"(arb[cur][mt][1]),
                          "r"(arb[cur][mt][2]), "r"(arb[cur][mt][3]),
                          "r"(b0), "r"(b1));
                }
        }
        // no bottom barrier: next iteration's top barrier orders buffer reuse
    }

    const int r0 = bm + wm + (lane >> 2);
    const int c0 = bn + wn + (lane & 3) * 2;
#pragma unroll
    for (int nt = 0; nt < NT; nt++) {
        int col = c0 + nt * 8;
        float2 bb = *(const float2*)(bias + col);
#pragma unroll
        for (int mt = 0; mt < MT; mt++) {
            int row = r0 + mt * 16;
            float2 v0 = make_float2(acc[mt][nt][0] + bb.x, acc[mt][nt][1] + bb.y);
            float2 v1 = make_float2(acc[mt][nt][2] + bb.x, acc[mt][nt][3] + bb.y);
            if (HALFOUT) {
                *(__half2*)(Ch + (size_t)row * ldc + col) = __floats2half2_rn(v0.x, v0.y);
                *(__half2*)(Ch + (size_t)(row + 8) * ldc + col) = __floats2half2_rn(v1.x, v1.y);
            } else {
                *(float2*)(Cf + (size_t)row * ldc + col) = v0;
                *(float2*)(Cf + (size_t)(row + 8) * ldc + col) = v1;
            }
        }
    }
}

// ---------------------------------------------------------------------------
// Tensor-core attention (unchanged from passing R16 kernel).
// Q, K, V fp16 from fused QKVh (stride 1536). O -> g_Xh fp16 (stride 512).
// ---------------------------------------------------------------------------
#define ATTN_SMEM (2 * MAXC * 128 + 8 * 2048)   // K 48K + V 48K + Q 16K = 112K

__global__ __launch_bounds__(256, 2) void attn_tc(
    const __half* __restrict__ QKVh, __half* __restrict__ Oh)
{
    extern __shared__ __align__(16) char smraw[];
    char* Kc = smraw;                     // [MAXC][128B]
    char* Vc = smraw + MAXC * 128;
    char* Qc = smraw + 2 * MAXC * 128;    // 8 warps x 2048B
    const uint32_t sK = smem_u32(Kc);
    const uint32_t sV = smem_u32(Vc);
    const uint32_t sQ = smem_u32(Qc);

    const int g = blockIdx.x, h = blockIdx.y;
    const int st = g_start[g];
    const int c = g_start[g + 1] - st;
    if (c <= 0) return;
    const int c16 = (c + 15) & ~15;
    const int nkt = c16 >> 4;
    const float fnpad = (float)(c16 - c);
    const int tid = threadIdx.x, wid = tid >> 5, lane = tid & 31;

    for (int idx = tid; idx < c16 * 8; idx += 256) {
        int r = idx >> 3, u = idx & 7;
        uint32_t off = r * 128 + ((u ^ (r & 7)) * 16);
        uint4 kv = make_uint4(0, 0, 0, 0), vv = make_uint4(0, 0, 0, 0);
        if (r < c) {
            const __half* src = QKVh + (size_t)(st + r) * 1536 + 512 + h * HDIM + u * 8;
            kv = *(const uint4*)src;
            vv = *(const uint4*)(src + 512);
        }
        *(uint4*)(Kc + off) = kv;
        *(uint4*)(Vc + off) = vv;
    }
    __syncthreads();

    const int lrow = lane & 15;
    const int lseg = lane >> 4;
    const int ntiles = (c + 15) >> 4;
    const uint32_t qb32 = sQ + wid * 2048;
    char* qbc = Qc + wid * 2048;
    const float scale = 0.125f;

    for (int qt = wid; qt < ntiles; qt += 8) {
        for (int t = lane; t < 128; t += 32) {
            int row = t & 15, seg = t >> 4;
            int qrow = qt * 16 + row;
            if (qrow >= c) qrow = c - 1;
            uint4 pk = *(const uint4*)(QKVh + (size_t)(st + qrow) * 1536 + h * HDIM + seg * 8);
            *(uint4*)(qbc + row * 128 + ((seg ^ (row & 7)) * 16)) = pk;
        }
        __syncwarp();

        uint32_t aq[4][4];
#pragma unroll
        for (int ks = 0; ks < 4; ks++) {
            uint32_t addr = qb32 + lrow * 128 + (((ks * 2 + lseg) ^ (lrow & 7)) * 16);
            asm volatile("ldmatrix.sync.aligned.m8n8.x4.shared.b16 {%0,%1,%2,%3}, [%4];"
                         : "=r"(aq[ks][0]), "=r"(aq[ks][1]), "=r"(aq[ks][2]), "=r"(aq[ks][3])
                         : "r"(addr));
        }

        float oacc[8][4];
#pragma unroll
        for (int d = 0; d < 8; d++)
#pragma unroll
            for (int e = 0; e < 4; e++) oacc[d][e] = 0.f;
        float lr = 0.f, lr8 = 0.f;

        for (int kt = 0; kt < nkt; kt++) {
            const int krow = kt * 16 + lrow;
            float sacc[2][4];
#pragma unroll
            for (int nt = 0; nt < 2; nt++)
#pragma unroll
                for (int e = 0; e < 4; e++) sacc[nt][e] = 0.f;
#pragma unroll
            for (int ks = 0; ks < 4; ks++) {
                uint32_t addr = sK + krow * 128 + (((ks * 2 + lseg) ^ (krow & 7)) * 16);
                uint32_t bk[4];
                asm volatile("ldmatrix.sync.aligned.m8n8.x4.shared.b16 {%0,%1,%2,%3}, [%4];"
                             : "=r"(bk[0]), "=r"(bk[1]), "=r"(bk[2]), "=r"(bk[3])
                             : "r"(addr));
#pragma unroll
                for (int nt = 0; nt < 2; nt++) {
                    asm volatile(
                        "mma.sync.aligned.m16n8k16.row.col.f32.f16.f16.f32 "
                        "{%0,%1,%2,%3}, {%4,%5,%6,%7}, {%8,%9}, {%0,%1,%2,%3};"
                        : "+f"(sacc[nt][0]), "+f"(sacc[nt][1]),
                          "+f"(sacc[nt][2]), "+f"(sacc[nt][3])
                        : "r"(aq[ks][0]), "r"(aq[ks][1]), "r"(aq[ks][2]), "r"(aq[ks][3]),
                          "r"(bk[nt]), "r"(bk[nt + 2]));
                }
            }
            float p00 = __expf(fminf(sacc[0][0] * scale, 10.f));
            float p01 = __expf(fminf(sacc[0][1] * scale, 10.f));
            float p02 = __expf(fminf(sacc[0][2] * scale, 10.f));
            float p03 = __expf(fminf(sacc[0][3] * scale, 10.f));
            float p10 = __expf(fminf(sacc[1][0] * scale, 10.f));
            float p11 = __expf(fminf(sacc[1][1] * scale, 10.f));
            float p12 = __expf(fminf(sacc[1][2] * scale, 10.f));
            float p13 = __expf(fminf(sacc[1][3] * scale, 10.f));
            __half2 a0 = __floats2half2_rn(p00, p01);
            __half2 a1 = __floats2half2_rn(p02, p03);
            __half2 a2 = __floats2half2_rn(p10, p11);
            __half2 a3 = __floats2half2_rn(p12, p13);
            float2 f;
            f = __half22float2(a0); lr += f.x + f.y;
            f = __half22float2(a1); lr8 += f.x + f.y;
            f = __half22float2(a2); lr += f.x + f.y;
            f = __half22float2(a3); lr8 += f.x + f.y;
            uint32_t pa0 = *(uint32_t*)&a0, pa1 = *(uint32_t*)&a1;
            uint32_t pa2 = *(uint32_t*)&a2, pa3 = *(uint32_t*)&a3;

#pragma unroll
            for (int v16 = 0; v16 < 4; v16++) {
                uint32_t addr = sV + krow * 128 + (((v16 * 2 + lseg) ^ (krow & 7)) * 16);
                uint32_t bv[4];
                asm volatile("ldmatrix.sync.aligned.m8n8.x4.trans.shared.b16 {%0,%1,%2,%3}, [%4];"
                             : "=r"(bv[0]), "=r"(bv[1]), "=r"(bv[2]), "=r"(bv[3])
                             : "r"(addr));
                asm volatile(
                    "mma.sync.aligned.m16n8k16.row.col.f32.f16.f16.f32 "
                    "{%0,%1,%2,%3}, {%4,%5,%6,%7}, {%8,%9}, {%0,%1,%2,%3};"
                    : "+f"(oacc[v16 * 2][0]), "+f"(oacc[v16 * 2][1]),
                      "+f"(oacc[v16 * 2][2]), "+f"(oacc[v16 * 2][3])
                    : "r"(pa0), "r"(pa1), "r"(pa2), "r"(pa3),
                      "r"(bv[0]), "r"(bv[1]));
                asm volatile(
                    "mma.sync.aligned.m16n8k16.row.col.f32.f16.f16.f32 "
                    "{%0,%1,%2,%3}, {%4,%5,%6,%7}, {%8,%9}, {%0,%1,%2,%3};"
                    : "+f"(oacc[v16 * 2 + 1][0]), "+f"(oacc[v16 * 2 + 1][1]),
                      "+f"(oacc[v16 * 2 + 1][2]), "+f"(oacc[v16 * 2 + 1][3])
                    : "r"(pa0), "r"(pa1), "r"(pa2), "r"(pa3),
                      "r"(bv[2]), "r"(bv[3]));
            }
        }

        lr += __shfl_xor_sync(0xffffffffu, lr, 1);
        lr += __shfl_xor_sync(0xffffffffu, lr, 2);
        lr8 += __shfl_xor_sync(0xffffffffu, lr8, 1);
        lr8 += __shfl_xor_sync(0xffffffffu, lr8, 2);
        float inv = 1.f / (lr - fnpad);
        float inv8 = 1.f / (lr8 - fnpad);

        const int r0 = qt * 16 + (lane >> 2);
#pragma unroll
        for (int dt = 0; dt < 8; dt++) {
            int col = h * HDIM + dt * 8 + (lane & 3) * 2;
            if (r0 < c)
                *(__half2*)(Oh + (size_t)(st + r0) * HID + col) =
                    __floats2half2_rn(oacc[dt][0] * inv, oacc[dt][1] * inv);
            if (r0 + 8 < c)
                *(__half2*)(Oh + (size_t)(st + r0 + 8) * HID + col) =
                    __floats2half2_rn(oacc[dt][2] * inv8, oacc[dt][3] * inv8);
        }
    }
}

// ---------------------------------------------------------------------------
extern "C" void kernel_launch(void* const* d_in, const int* in_sizes, int n_in,
                              void* d_out, int out_size) {
    const float* x  = (const float*)d_in[0];
    const void*  bt = d_in[1];
    const float* wq = (const float*)d_in[2];
    const float* bq = (const float*)d_in[3];
    const float* wk = (const float*)d_in[4];
    const float* bk = (const float*)d_in[5];
    const float* wv = (const float*)d_in[6];
    const float* bv = (const float*)d_in[7];
    const float* wo = (const float*)d_in[8];
    const float* bo = (const float*)d_in[9];
    float* out = (float*)d_out;

    float* bcat;
    __half *QKVh, *Xh, *Wh;
    cudaGetSymbolAddress((void**)&QKVh, g_QKVh);
    cudaGetSymbolAddress((void**)&Xh, g_Xh);
    cudaGetSymbolAddress((void**)&Wh, g_Wh);
    cudaGetSymbolAddress((void**)&bcat, g_bcat);
    __half* Who = Wh + 3 * (size_t)HID * HID;

    const int smemQKV = NSTAGE * (64 * 128 + 128 * 128);  // 49152
    const int smemOut = NSTAGE * (64 * 128 + 64 * 128);   // 32768
    cudaFuncSetAttribute((const void*)gemm_hmma<64, 128, true>,
                         cudaFuncAttributeMaxDynamicSharedMemorySize, smemQKV);
    cudaFuncSetAttribute((const void*)gemm_hmma<64, 64, false>,
                         cudaFuncAttributeMaxDynamicSharedMemorySize, smemOut);
    cudaFuncSetAttribute(attn_tc,
                         cudaFuncAttributeMaxDynamicSharedMemorySize, ATTN_SMEM);

    // fused prep: W/x fp16 convert + segment starts + bias concat
    prep_kernel<<<(PREP_TOT + 255) / 256, 256>>>(
        x, bt, wq, wk, wv, wo, bq, bk, bv, Xh, Wh);

    // fused Q|K|V projection: N = 1536, K = 512, fp16 out (BM=64)
    gemm_hmma<64, 128, true><<<dim3(12, 160), 128, smemQKV>>>(
        Xh, Wh, bcat, nullptr, QKVh, 1536);

    // tensor-core attention; O -> Xh (fp16)
    attn_tc<<<dim3(NGRAPH, HEADS), 256, ATTN_SMEM>>>(QKVh, Xh);

    // output projection: K = 512, fp32 out (BM=64, BN=64)
    gemm_hmma<64, 64, false><<<dim3(8, 160), 128, smemOut>>>(
        Xh, Who, bo, out, nullptr, 512);
}